// round 7
// baseline (speedup 1.0000x reference)
#include <cuda_runtime.h>
#include <cuda_bf16.h>
#include <math.h>
#include <stdint.h>

// Problem constants
#define BATCH 16
#define THW   2048
#define TF    2048
#define CDIM  512

#define NELEM_QK (BATCH * THW * CDIM)
#define NELEM_SC ((size_t)BATCH * THW * (size_t)TF)

// ---------------------------------------------------------------------------
// Scratch (device globals — no allocations allowed)
// ---------------------------------------------------------------------------
__device__ float g_qin[NELEM_QK];                 // fp32 q-projection (residual)
__device__ float g_sc [NELEM_SC];                 // fp32 scores
__device__ __nv_bfloat16 g_qh [NELEM_QK], g_ql [NELEM_QK];
__device__ __nv_bfloat16 g_kh [NELEM_QK], g_kl [NELEM_QK];
__device__ __nv_bfloat16 g_Wqh[CDIM*CDIM], g_Wql[CDIM*CDIM];
__device__ __nv_bfloat16 g_Wkh[CDIM*CDIM], g_Wkl[CDIM*CDIM];
__device__ __nv_bfloat16 g_Wvh[CDIM*CDIM], g_Wvl[CDIM*CDIM];
__device__ __nv_bfloat16 g_qinh[NELEM_QK], g_qinl[NELEM_QK];
__device__ __nv_bfloat16 g_kph [NELEM_QK], g_kpl [NELEM_QK]; // [b][t][c]
__device__ __nv_bfloat16 g_vph [NELEM_QK], g_vpl [NELEM_QK]; // [b][t][c]
__device__ __nv_bfloat16 g_sch [NELEM_SC], g_scl [NELEM_SC];

// ---------------------------------------------------------------------------
// GEMM config: 128x128 tile, BK=32 chunks, 256 threads = 8 warps (2m x 4n),
// warp tile 64x32, 4-stage cp.async pipeline.
// ---------------------------------------------------------------------------
#define BK 32
#define LDA_S 40                   // padded A row stride (bf16)
#define LDB_S 136                  // padded B row stride (bf16)
#define A_BYTES (128 * LDA_S * 2)  // 10240
#define B_BYTES (BK * LDB_S * 2)   // 8704
#define STAGE_B (2 * A_BYTES + 2 * B_BYTES)   // 37888
#define NSTAGE 4
#define SMEM_GEMM (NSTAGE * STAGE_B)          // 151552 = 148 KB

__device__ __forceinline__ void ldsm4(uint32_t* r, uint32_t addr) {
    asm volatile("ldmatrix.sync.aligned.m8n8.x4.shared.b16 {%0,%1,%2,%3}, [%4];\n"
                 : "=r"(r[0]), "=r"(r[1]), "=r"(r[2]), "=r"(r[3]) : "r"(addr));
}
__device__ __forceinline__ void ldsm4t(uint32_t* r, uint32_t addr) {
    asm volatile("ldmatrix.sync.aligned.m8n8.x4.trans.shared.b16 {%0,%1,%2,%3}, [%4];\n"
                 : "=r"(r[0]), "=r"(r[1]), "=r"(r[2]), "=r"(r[3]) : "r"(addr));
}
__device__ __forceinline__ void mma16816(float* c, const uint32_t* a, const uint32_t* b) {
    asm volatile("mma.sync.aligned.m16n8k16.row.col.f32.bf16.bf16.f32 "
                 "{%0,%1,%2,%3},{%4,%5,%6,%7},{%8,%9},{%0,%1,%2,%3};\n"
                 : "+f"(c[0]), "+f"(c[1]), "+f"(c[2]), "+f"(c[3])
                 : "r"(a[0]), "r"(a[1]), "r"(a[2]), "r"(a[3]), "r"(b[0]), "r"(b[1]));
}
__device__ __forceinline__ void cp16(uint32_t dst, const void* src) {
    asm volatile("cp.async.cg.shared.global [%0], [%1], 16;\n" :: "r"(dst), "l"(src));
}
__device__ __forceinline__ void cp_commit() {
    asm volatile("cp.async.commit_group;\n" ::: "memory");
}
template <int N>
__device__ __forceinline__ void cp_wait() {
    asm volatile("cp.async.wait_group %0;\n" :: "n"(N) : "memory");
}

__global__ __launch_bounds__(256, 1) void mma_gemm(
    const __nv_bfloat16* __restrict__ Ahg, const __nv_bfloat16* __restrict__ Alg,
    const __nv_bfloat16* __restrict__ Bhg, const __nv_bfloat16* __restrict__ Blg,
    const float* __restrict__ bias, const float* __restrict__ resid,
    float* __restrict__ Cf, __nv_bfloat16* __restrict__ Ch, __nv_bfloat16* __restrict__ Cl,
    int K, int lda, int ldb, int ldc,
    long long sA, long long sB, long long sC, long long sR)
{
    extern __shared__ char smem[];
    const uint32_t smem_u32 = (uint32_t)__cvta_generic_to_shared(smem);

    const long long bz = blockIdx.z;
    Ahg += bz * sA; Alg += bz * sA;
    Bhg += bz * sB; Blg += bz * sB;
    if (Cf)    Cf    += bz * sC;
    if (Ch)  { Ch    += bz * sC; Cl += bz * sC; }
    if (resid) resid += bz * sR;

    const int tid  = threadIdx.x;
    const int warp = tid >> 5;
    const int lane = tid & 31;
    const int wm = warp >> 2;
    const int wn = warp & 3;
    const int g   = lane >> 2;
    const int tig = lane & 3;

    const int row0 = blockIdx.y * 128;
    const int col0 = blockIdx.x * 128;

    // cp.async load maps
    const int ar = tid >> 1;             // A row 0..127
    const int acb = (tid & 1) * 32;      // A byte col {0,32}, +16 inner
    const int br = tid >> 3;             // B row 0..31
    const int bcb = (tid & 7) * 32;      // B byte col, +16 inner

    // ldmatrix fragment address components (verified in R4)
    const int a_r = wm * 64 + (lane & 15);
    const int a_c = (lane >> 4) * 8;
    const int b_r = lane & 15;
    const int b_c = wn * 32 + ((lane & 16) ? 8 : 0);

    float acc[4][4][4];
    #pragma unroll
    for (int i = 0; i < 4; i++)
        #pragma unroll
        for (int j = 0; j < 4; j++)
            #pragma unroll
            for (int l = 0; l < 4; l++) acc[i][j][l] = 0.0f;

    const int NC = K / BK;

    // ---- stage loader ----
    auto load_stage = [&](int stage, int chunk) {
        const uint32_t sb = smem_u32 + stage * STAGE_B;
        const int k0 = chunk * BK;
        #pragma unroll
        for (int i = 0; i < 2; i++) {
            const int cb = acb + i * 16;                       // bytes in [0,64)
            const long long ao = (long long)(row0 + ar) * lda + k0 + (cb >> 1);
            const uint32_t ad = sb + ar * (LDA_S * 2) + cb;
            cp16(ad,            Ahg + ao);
            cp16(ad + A_BYTES,  Alg + ao);
        }
        #pragma unroll
        for (int i = 0; i < 2; i++) {
            const int cb = bcb + i * 16;                       // bytes in [0,256)
            const long long bo = (long long)(k0 + br) * ldb + col0 + (cb >> 1);
            const uint32_t bd = sb + 2 * A_BYTES + br * (LDB_S * 2) + cb;
            cp16(bd,            Bhg + bo);
            cp16(bd + B_BYTES,  Blg + bo);
        }
    };

    // ---- prologue: fill NSTAGE-1 stages ----
    #pragma unroll
    for (int s = 0; s < NSTAGE - 1; s++) {
        if (s < NC) load_stage(s, s);
        cp_commit();
    }

    for (int c = 0; c < NC; c++) {
        cp_wait<NSTAGE - 2>();
        __syncthreads();

        // issue load for chunk c+NSTAGE-1 into the buffer just freed
        if (c + NSTAGE - 1 < NC) load_stage((c + NSTAGE - 1) % NSTAGE, c + NSTAGE - 1);
        cp_commit();

        const uint32_t sb  = smem_u32 + (c % NSTAGE) * STAGE_B;
        const uint32_t ah0 = sb;
        const uint32_t al0 = sb + A_BYTES;
        const uint32_t bh0 = sb + 2 * A_BYTES;
        const uint32_t bl0 = bh0 + B_BYTES;

        #pragma unroll
        for (int ks = 0; ks < 2; ks++) {
            uint32_t fah[4][4], fbh[4][2];
            #pragma unroll
            for (int mt = 0; mt < 4; mt++)
                ldsm4(fah[mt], ah0 + 2 * ((a_r + mt * 16) * LDA_S + a_c + ks * 16));
            {
                uint32_t t[4];
                ldsm4t(t, bh0 + 2 * ((ks * 16 + b_r) * LDB_S + b_c));
                fbh[0][0] = t[0]; fbh[0][1] = t[1]; fbh[1][0] = t[2]; fbh[1][1] = t[3];
                ldsm4t(t, bh0 + 2 * ((ks * 16 + b_r) * LDB_S + b_c + 16));
                fbh[2][0] = t[0]; fbh[2][1] = t[1]; fbh[3][0] = t[2]; fbh[3][1] = t[3];
            }
            #pragma unroll
            for (int mt = 0; mt < 4; mt++)
                #pragma unroll
                for (int nt = 0; nt < 4; nt++)
                    mma16816(acc[mt][nt], fah[mt], fbh[nt]);

            {
                uint32_t fbl[4][2];
                uint32_t t[4];
                ldsm4t(t, bl0 + 2 * ((ks * 16 + b_r) * LDB_S + b_c));
                fbl[0][0] = t[0]; fbl[0][1] = t[1]; fbl[1][0] = t[2]; fbl[1][1] = t[3];
                ldsm4t(t, bl0 + 2 * ((ks * 16 + b_r) * LDB_S + b_c + 16));
                fbl[2][0] = t[0]; fbl[2][1] = t[1]; fbl[3][0] = t[2]; fbl[3][1] = t[3];
                #pragma unroll
                for (int mt = 0; mt < 4; mt++)
                    #pragma unroll
                    for (int nt = 0; nt < 4; nt++)
                        mma16816(acc[mt][nt], fah[mt], fbl[nt]);
            }
            {
                uint32_t fal[4];
                #pragma unroll
                for (int mt = 0; mt < 4; mt++) {
                    ldsm4(fal, al0 + 2 * ((a_r + mt * 16) * LDA_S + a_c + ks * 16));
                    #pragma unroll
                    for (int nt = 0; nt < 4; nt++)
                        mma16816(acc[mt][nt], fal, fbh[nt]);
                }
            }
        }
    }

    // ---- epilogue (direct writes; mapping verified in R4) ----
    #pragma unroll
    for (int mt = 0; mt < 4; mt++) {
        #pragma unroll
        for (int nt = 0; nt < 4; nt++) {
            const int r = row0 + wm * 64 + mt * 16 + g;
            const int c = col0 + wn * 32 + nt * 8 + 2 * tig;
            float2 v0 = make_float2(acc[mt][nt][0], acc[mt][nt][1]);
            float2 v1 = make_float2(acc[mt][nt][2], acc[mt][nt][3]);
            if (bias) {
                const float b0 = bias[c], b1 = bias[c + 1];
                v0.x += b0; v0.y += b1;
                v1.x += b0; v1.y += b1;
            }
            if (resid) {
                const float2 r0v = *reinterpret_cast<const float2*>(&resid[(long long)r * ldc + c]);
                const float2 r1v = *reinterpret_cast<const float2*>(&resid[(long long)(r + 8) * ldc + c]);
                v0.x += r0v.x; v0.y += r0v.y;
                v1.x += r1v.x; v1.y += r1v.y;
            }
            if (Cf) {
                *reinterpret_cast<float2*>(&Cf[(long long)r * ldc + c]) = v0;
                *reinterpret_cast<float2*>(&Cf[(long long)(r + 8) * ldc + c]) = v1;
            }
            if (Ch) {
                const __nv_bfloat16 h0 = __float2bfloat16(v0.x);
                const __nv_bfloat16 h1 = __float2bfloat16(v0.y);
                const __nv_bfloat16 h2 = __float2bfloat16(v1.x);
                const __nv_bfloat16 h3 = __float2bfloat16(v1.y);
                *reinterpret_cast<__nv_bfloat162*>(&Ch[(long long)r * ldc + c]) =
                    __halves2bfloat162(h0, h1);
                *reinterpret_cast<__nv_bfloat162*>(&Ch[(long long)(r + 8) * ldc + c]) =
                    __halves2bfloat162(h2, h3);
                *reinterpret_cast<__nv_bfloat162*>(&Cl[(long long)r * ldc + c]) =
                    __halves2bfloat162(__float2bfloat16(v0.x - __bfloat162float(h0)),
                                       __float2bfloat16(v0.y - __bfloat162float(h1)));
                *reinterpret_cast<__nv_bfloat162*>(&Cl[(long long)(r + 8) * ldc + c]) =
                    __halves2bfloat162(__float2bfloat16(v1.x - __bfloat162float(h2)),
                                       __float2bfloat16(v1.y - __bfloat162float(h3)));
            }
        }
    }
}

// ---------------------------------------------------------------------------
// fp32 -> bf16 hi/lo elementwise split
// ---------------------------------------------------------------------------
__global__ __launch_bounds__(256) void split_kernel(
    const float* __restrict__ x, __nv_bfloat16* __restrict__ h,
    __nv_bfloat16* __restrict__ l, int n4)
{
    const int idx = blockIdx.x * 256 + threadIdx.x;
    if (idx >= n4) return;
    const float4 v = reinterpret_cast<const float4*>(x)[idx];
    __nv_bfloat16 h0 = __float2bfloat16(v.x), h1 = __float2bfloat16(v.y);
    __nv_bfloat16 h2 = __float2bfloat16(v.z), h3 = __float2bfloat16(v.w);
    reinterpret_cast<__nv_bfloat162*>(h)[idx * 2]     = __halves2bfloat162(h0, h1);
    reinterpret_cast<__nv_bfloat162*>(h)[idx * 2 + 1] = __halves2bfloat162(h2, h3);
    reinterpret_cast<__nv_bfloat162*>(l)[idx * 2] = __halves2bfloat162(
        __float2bfloat16(v.x - __bfloat162float(h0)),
        __float2bfloat16(v.y - __bfloat162float(h1)));
    reinterpret_cast<__nv_bfloat162*>(l)[idx * 2 + 1] = __halves2bfloat162(
        __float2bfloat16(v.z - __bfloat162float(h2)),
        __float2bfloat16(v.w - __bfloat162float(h3)));
}

// ---------------------------------------------------------------------------
// Row softmax over TF with bf16 hi/lo split output
// ---------------------------------------------------------------------------
__global__ __launch_bounds__(256) void softmax_split(
    const float* __restrict__ S, __nv_bfloat16* __restrict__ H,
    __nv_bfloat16* __restrict__ L)
{
    const long long row = blockIdx.x;
    const float* p = S + row * (long long)TF;
    const int tid = threadIdx.x;
    __shared__ float red[32];

    float4 v0 = *reinterpret_cast<const float4*>(&p[tid * 8]);
    float4 v1 = *reinterpret_cast<const float4*>(&p[tid * 8 + 4]);

    float lmax = fmaxf(fmaxf(fmaxf(v0.x, v0.y), fmaxf(v0.z, v0.w)),
                       fmaxf(fmaxf(v1.x, v1.y), fmaxf(v1.z, v1.w)));
    #pragma unroll
    for (int o = 16; o; o >>= 1) lmax = fmaxf(lmax, __shfl_xor_sync(0xffffffffu, lmax, o));
    if ((tid & 31) == 0) red[tid >> 5] = lmax;
    __syncthreads();
    if (tid < 32) {
        float v = (tid < 8) ? red[tid] : -INFINITY;
        #pragma unroll
        for (int o = 4; o; o >>= 1) v = fmaxf(v, __shfl_xor_sync(0xffffffffu, v, o));
        if (tid == 0) red[0] = v;
    }
    __syncthreads();
    const float mx = red[0];
    __syncthreads();

    v0.x = __expf(v0.x - mx); v0.y = __expf(v0.y - mx);
    v0.z = __expf(v0.z - mx); v0.w = __expf(v0.w - mx);
    v1.x = __expf(v1.x - mx); v1.y = __expf(v1.y - mx);
    v1.z = __expf(v1.z - mx); v1.w = __expf(v1.w - mx);
    float lsum = (v0.x + v0.y + v0.z + v0.w) + (v1.x + v1.y + v1.z + v1.w);
    #pragma unroll
    for (int o = 16; o; o >>= 1) lsum += __shfl_xor_sync(0xffffffffu, lsum, o);
    if ((tid & 31) == 0) red[tid >> 5] = lsum;
    __syncthreads();
    if (tid < 32) {
        float v = (tid < 8) ? red[tid] : 0.0f;
        #pragma unroll
        for (int o = 4; o; o >>= 1) v += __shfl_xor_sync(0xffffffffu, v, o);
        if (tid == 0) red[0] = v;
    }
    __syncthreads();
    const float inv = 1.0f / red[0];

    float vv[8] = { v0.x * inv, v0.y * inv, v0.z * inv, v0.w * inv,
                    v1.x * inv, v1.y * inv, v1.z * inv, v1.w * inv };
    __nv_bfloat16* hp = H + row * (long long)TF + tid * 8;
    __nv_bfloat16* lp = L + row * (long long)TF + tid * 8;
    #pragma unroll
    for (int e = 0; e < 8; e += 2) {
        const __nv_bfloat16 h0 = __float2bfloat16(vv[e]);
        const __nv_bfloat16 h1 = __float2bfloat16(vv[e + 1]);
        *reinterpret_cast<__nv_bfloat162*>(hp + e) = __halves2bfloat162(h0, h1);
        *reinterpret_cast<__nv_bfloat162*>(lp + e) = __halves2bfloat162(
            __float2bfloat16(vv[e] - __bfloat162float(h0)),
            __float2bfloat16(vv[e + 1] - __bfloat162float(h1)));
    }
}

// ---------------------------------------------------------------------------
// kernel_launch
// ---------------------------------------------------------------------------
extern "C" void kernel_launch(void* const* d_in, const int* in_sizes, int n_in,
                              void* d_out, int out_size)
{
    const float* q  = (const float*)d_in[0];
    const float* k  = (const float*)d_in[1];
    const float* Wq = (const float*)d_in[2];
    const float* bq = (const float*)d_in[3];
    const float* Wk = (const float*)d_in[4];
    const float* bk = (const float*)d_in[5];
    const float* Wv = (const float*)d_in[6];
    const float* bv = (const float*)d_in[7];
    float* out = (float*)d_out;

    void* p;
    cudaGetSymbolAddress(&p, g_qin);  float* qin = (float*)p;
    cudaGetSymbolAddress(&p, g_sc);   float* sc  = (float*)p;
    cudaGetSymbolAddress(&p, g_qh);   __nv_bfloat16* qh = (__nv_bfloat16*)p;
    cudaGetSymbolAddress(&p, g_ql);   __nv_bfloat16* ql = (__nv_bfloat16*)p;
    cudaGetSymbolAddress(&p, g_kh);   __nv_bfloat16* kh = (__nv_bfloat16*)p;
    cudaGetSymbolAddress(&p, g_kl);   __nv_bfloat16* kl = (__nv_bfloat16*)p;
    cudaGetSymbolAddress(&p, g_Wqh);  __nv_bfloat16* Wqh = (__nv_bfloat16*)p;
    cudaGetSymbolAddress(&p, g_Wql);  __nv_bfloat16* Wql = (__nv_bfloat16*)p;
    cudaGetSymbolAddress(&p, g_Wkh);  __nv_bfloat16* Wkh = (__nv_bfloat16*)p;
    cudaGetSymbolAddress(&p, g_Wkl);  __nv_bfloat16* Wkl = (__nv_bfloat16*)p;
    cudaGetSymbolAddress(&p, g_Wvh);  __nv_bfloat16* Wvh = (__nv_bfloat16*)p;
    cudaGetSymbolAddress(&p, g_Wvl);  __nv_bfloat16* Wvl = (__nv_bfloat16*)p;
    cudaGetSymbolAddress(&p, g_qinh); __nv_bfloat16* qinh = (__nv_bfloat16*)p;
    cudaGetSymbolAddress(&p, g_qinl); __nv_bfloat16* qinl = (__nv_bfloat16*)p;
    cudaGetSymbolAddress(&p, g_kph);  __nv_bfloat16* kph  = (__nv_bfloat16*)p;
    cudaGetSymbolAddress(&p, g_kpl);  __nv_bfloat16* kpl  = (__nv_bfloat16*)p;
    cudaGetSymbolAddress(&p, g_vph);  __nv_bfloat16* vph  = (__nv_bfloat16*)p;
    cudaGetSymbolAddress(&p, g_vpl);  __nv_bfloat16* vpl  = (__nv_bfloat16*)p;
    cudaGetSymbolAddress(&p, g_sch);  __nv_bfloat16* sch  = (__nv_bfloat16*)p;
    cudaGetSymbolAddress(&p, g_scl);  __nv_bfloat16* scl  = (__nv_bfloat16*)p;

    cudaFuncSetAttribute(mma_gemm, cudaFuncAttributeMaxDynamicSharedMemorySize,
                         SMEM_GEMM);

    // 1. split inputs + weights
    {
        const int n4 = NELEM_QK / 4;
        split_kernel<<<n4 / 256, 256>>>(q, qh, ql, n4);
        split_kernel<<<n4 / 256, 256>>>(k, kh, kl, n4);
        const int w4 = CDIM * CDIM / 4;
        split_kernel<<<w4 / 256, 256>>>(Wq, Wqh, Wql, w4);
        split_kernel<<<w4 / 256, 256>>>(Wk, Wkh, Wkl, w4);
        split_kernel<<<w4 / 256, 256>>>(Wv, Wvh, Wvl, w4);
    }
    // 2. projections: [32768,512] x [512,512]
    {
        const dim3 grd(CDIM / 128, (BATCH * THW) / 128, 1);
        mma_gemm<<<grd, 256, SMEM_GEMM>>>(qh, ql, Wqh, Wql, bq, nullptr,
                                          qin, qinh, qinl,
                                          CDIM, CDIM, CDIM, CDIM, 0, 0, 0, 0);
        mma_gemm<<<grd, 256, SMEM_GEMM>>>(kh, kl, Wkh, Wkl, bk, nullptr,
                                          nullptr, kph, kpl,
                                          CDIM, CDIM, CDIM, CDIM, 0, 0, 0, 0);
        mma_gemm<<<grd, 256, SMEM_GEMM>>>(kh, kl, Wvh, Wvl, bv, nullptr,
                                          nullptr, vph, vpl,
                                          CDIM, CDIM, CDIM, CDIM, 0, 0, 0, 0);
    }
    // 3. scores: qin (lda=512) x kp raw-view (ldb=TF)
    {
        const dim3 grd(TF / 128, THW / 128, BATCH);
        mma_gemm<<<grd, 256, SMEM_GEMM>>>(qinh, qinl, kph, kpl, nullptr, nullptr,
                                          sc, nullptr, nullptr,
                                          CDIM, CDIM, TF, TF,
                                          (long long)THW * CDIM,
                                          (long long)TF * CDIM,
                                          (long long)THW * TF, 0);
    }
    // 4. softmax + split
    softmax_split<<<BATCH * THW, 256>>>(sc, sch, scl);
    // 5. output: attn (lda=TF) x vp (ldb=CDIM) + qin residual
    {
        const dim3 grd(CDIM / 128, THW / 128, BATCH);
        mma_gemm<<<grd, 256, SMEM_GEMM>>>(sch, scl, vph, vpl, nullptr, qin,
                                          out, nullptr, nullptr,
                                          TF, TF, CDIM, CDIM,
                                          (long long)THW * TF,
                                          (long long)TF * CDIM,
                                          (long long)THW * CDIM,
                                          (long long)THW * CDIM);
    }
}

// round 8
// speedup vs baseline: 1.1411x; 1.1411x over previous
#include <cuda_runtime.h>
#include <cuda_fp16.h>
#include <math.h>
#include <stdint.h>

// Problem constants
#define BATCH 16
#define THW   2048
#define TF    2048
#define CDIM  512

#define NELEM_QK (BATCH * THW * CDIM)
#define NELEM_SC ((size_t)BATCH * THW * (size_t)TF)

// ---------------------------------------------------------------------------
// Scratch (device globals — no allocations allowed)
// ---------------------------------------------------------------------------
__device__ float g_qin[NELEM_QK];                 // fp32 q-projection (residual)
__device__ float g_sc [NELEM_SC];                 // fp32 scores
__device__ __half g_qh [NELEM_QK], g_ql [NELEM_QK];
__device__ __half g_kh [NELEM_QK], g_kl [NELEM_QK];
__device__ __half g_Wqh[CDIM*CDIM], g_Wql[CDIM*CDIM];
__device__ __half g_Wkh[CDIM*CDIM], g_Wkl[CDIM*CDIM];
__device__ __half g_Wvh[CDIM*CDIM], g_Wvl[CDIM*CDIM];
__device__ __half g_qinh[NELEM_QK], g_qinl[NELEM_QK];
__device__ __half g_kph [NELEM_QK], g_kpl [NELEM_QK]; // [b][t][c]
__device__ __half g_vph [NELEM_QK];                   // [b][t][c] hi only
__device__ __half g_sch [NELEM_SC], g_scl [NELEM_SC];

// ---------------------------------------------------------------------------
// GEMM config: 128x128 tile, BK=32, 256 threads = 8 warps (2m x 4n),
// warp tile 64x32, register-staged double buffer (R4 structure — measured best)
// ---------------------------------------------------------------------------
#define BK 32
#define LDA_S 40                    // padded A row stride (halves)
#define LDB_S 136                   // padded B row stride (halves)
#define A_HBYTES (128 * LDA_S * 2)  // 10240 bytes per A half-tile
#define B_HBYTES (BK * LDB_S * 2)   // 8704 bytes per B half-tile
// layout per buffer: [Ah][Al][Bh][Bl]; two buffers
#define BUF_BYTES (2 * A_HBYTES + 2 * B_HBYTES)   // 37888
#define SMEM_GEMM (2 * BUF_BYTES)                 // 75776

__device__ __forceinline__ void ldsm4(uint32_t* r, uint32_t addr) {
    asm volatile("ldmatrix.sync.aligned.m8n8.x4.shared.b16 {%0,%1,%2,%3}, [%4];\n"
                 : "=r"(r[0]), "=r"(r[1]), "=r"(r[2]), "=r"(r[3]) : "r"(addr));
}
__device__ __forceinline__ void ldsm4t(uint32_t* r, uint32_t addr) {
    asm volatile("ldmatrix.sync.aligned.m8n8.x4.trans.shared.b16 {%0,%1,%2,%3}, [%4];\n"
                 : "=r"(r[0]), "=r"(r[1]), "=r"(r[2]), "=r"(r[3]) : "r"(addr));
}
__device__ __forceinline__ void mma16816(float* c, const uint32_t* a, const uint32_t* b) {
    asm volatile("mma.sync.aligned.m16n8k16.row.col.f32.f16.f16.f32 "
                 "{%0,%1,%2,%3},{%4,%5,%6,%7},{%8,%9},{%0,%1,%2,%3};\n"
                 : "+f"(c[0]), "+f"(c[1]), "+f"(c[2]), "+f"(c[3])
                 : "r"(a[0]), "r"(a[1]), "r"(a[2]), "r"(a[3]), "r"(b[0]), "r"(b[1]));
}

template <int USE_BL>
__global__ __launch_bounds__(256, 1) void mma_gemm(
    const __half* __restrict__ Ahg, const __half* __restrict__ Alg,
    const __half* __restrict__ Bhg, const __half* __restrict__ Blg,
    const float* __restrict__ bias, const float* __restrict__ resid,
    float* __restrict__ Cf, __half* __restrict__ Ch, __half* __restrict__ Cl,
    int K, int lda, int ldb, int ldc,
    long long sA, long long sB, long long sC, long long sR)
{
    extern __shared__ char smem[];
    const uint32_t smem_u32 = (uint32_t)__cvta_generic_to_shared(smem);

    const long long bz = blockIdx.z;
    Ahg += bz * sA; Alg += bz * sA;
    Bhg += bz * sB; if (USE_BL) Blg += bz * sB;
    if (Cf)    Cf    += bz * sC;
    if (Ch)    Ch    += bz * sC;
    if (Cl)    Cl    += bz * sC;
    if (resid) resid += bz * sR;

    const int tid  = threadIdx.x;
    const int warp = tid >> 5;
    const int lane = tid & 31;
    const int wm = warp >> 2;
    const int wn = warp & 3;
    const int g   = lane >> 2;
    const int tig = lane & 3;

    const int row0 = blockIdx.y * 128;
    const int col0 = blockIdx.x * 128;

    // gmem load map: A half-tile 128x32 half = 64B/row, 2 threads/row
    const int ar  = tid >> 1;            // 0..127
    const int ab  = (tid & 1) * 32;      // byte offset {0,32}, +16 inner
    // B half-tile 32x128 half = 256B/row, 8 threads/row
    const int br  = tid >> 3;            // 0..31
    const int bb  = (tid & 7) * 32;      // byte offset, +16 inner

    // ldmatrix fragment address components (verified R4)
    const int a_r = wm * 64 + (lane & 15);
    const int a_c = (lane >> 4) * 8;
    const int b_r = lane & 15;
    const int b_c = wn * 32 + ((lane & 16) ? 8 : 0);

    float acc[4][4][4];
    #pragma unroll
    for (int i = 0; i < 4; i++)
        #pragma unroll
        for (int j = 0; j < 4; j++)
            #pragma unroll
            for (int l = 0; l < 4; l++) acc[i][j][l] = 0.0f;

    const int NC = K / BK;

    // smem section offsets within a buffer
    const uint32_t OFF_AL = A_HBYTES;
    const uint32_t OFF_BH = 2 * A_HBYTES;
    const uint32_t OFF_BL = 2 * A_HBYTES + B_HBYTES;

    // gmem element offsets (halves): A row = row0+ar, col = ab/2 + i*8
    // B row = k0+br, col = col0 + bb/2 + i*8

    // ---- prologue: chunk 0 -> buffer 0 (direct gmem->smem via regs) ----
    {
        const uint32_t sb = smem_u32;
        #pragma unroll
        for (int i = 0; i < 2; i++) {
            const long long ao = (long long)(row0 + ar) * lda + (ab >> 1) + i * 8;
            const uint32_t ad = sb + ar * (LDA_S * 2) + ab + i * 16;
            *(uint4*)(smem + (ad - smem_u32))            = *(const uint4*)(Ahg + ao);
            *(uint4*)(smem + (ad - smem_u32) + OFF_AL)   = *(const uint4*)(Alg + ao);
        }
        #pragma unroll
        for (int i = 0; i < 2; i++) {
            const long long bo = (long long)br * ldb + col0 + (bb >> 1) + i * 8;
            const uint32_t bd = sb + OFF_BH + br * (LDB_S * 2) + bb + i * 16;
            *(uint4*)(smem + (bd - smem_u32)) = *(const uint4*)(Bhg + bo);
            if (USE_BL)
                *(uint4*)(smem + (bd - smem_u32) + B_HBYTES) = *(const uint4*)(Blg + bo);
        }
    }
    __syncthreads();

    int buf = 0;
    for (int c = 0; c < NC; c++) {
        const bool has_next = (c + 1) < NC;
        uint4 pah[2], pal[2], pbh[2], pbl[2];
        if (has_next) {
            const int k0 = (c + 1) * BK;
            #pragma unroll
            for (int i = 0; i < 2; i++) {
                const long long ao = (long long)(row0 + ar) * lda + k0 + (ab >> 1) + i * 8;
                pah[i] = *(const uint4*)(Ahg + ao);
                pal[i] = *(const uint4*)(Alg + ao);
            }
            #pragma unroll
            for (int i = 0; i < 2; i++) {
                const long long bo = (long long)(k0 + br) * ldb + col0 + (bb >> 1) + i * 8;
                pbh[i] = *(const uint4*)(Bhg + bo);
                if (USE_BL) pbl[i] = *(const uint4*)(Blg + bo);
            }
        }

        // ---- compute on current buffer ----
        const uint32_t sb  = smem_u32 + buf * BUF_BYTES;
        const uint32_t ah0 = sb;
        const uint32_t al0 = sb + OFF_AL;
        const uint32_t bh0 = sb + OFF_BH;
        const uint32_t bl0 = sb + OFF_BL;

        #pragma unroll
        for (int ks = 0; ks < 2; ks++) {
            uint32_t fah[4][4], fbh[4][2];
            #pragma unroll
            for (int mt = 0; mt < 4; mt++)
                ldsm4(fah[mt], ah0 + 2 * ((a_r + mt * 16) * LDA_S + a_c + ks * 16));
            {
                uint32_t t[4];
                ldsm4t(t, bh0 + 2 * ((ks * 16 + b_r) * LDB_S + b_c));
                fbh[0][0] = t[0]; fbh[0][1] = t[1]; fbh[1][0] = t[2]; fbh[1][1] = t[3];
                ldsm4t(t, bh0 + 2 * ((ks * 16 + b_r) * LDB_S + b_c + 16));
                fbh[2][0] = t[0]; fbh[2][1] = t[1]; fbh[3][0] = t[2]; fbh[3][1] = t[3];
            }
            // P1: Ah * Bh
            #pragma unroll
            for (int mt = 0; mt < 4; mt++)
                #pragma unroll
                for (int nt = 0; nt < 4; nt++)
                    mma16816(acc[mt][nt], fah[mt], fbh[nt]);

            // P2: Ah * Bl (only when 3-pass)
            if (USE_BL) {
                uint32_t fbl[4][2];
                uint32_t t[4];
                ldsm4t(t, bl0 + 2 * ((ks * 16 + b_r) * LDB_S + b_c));
                fbl[0][0] = t[0]; fbl[0][1] = t[1]; fbl[1][0] = t[2]; fbl[1][1] = t[3];
                ldsm4t(t, bl0 + 2 * ((ks * 16 + b_r) * LDB_S + b_c + 16));
                fbl[2][0] = t[0]; fbl[2][1] = t[1]; fbl[3][0] = t[2]; fbl[3][1] = t[3];
                #pragma unroll
                for (int mt = 0; mt < 4; mt++)
                    #pragma unroll
                    for (int nt = 0; nt < 4; nt++)
                        mma16816(acc[mt][nt], fah[mt], fbl[nt]);
            }
            // P3: Al * Bh (always — keeps A exact)
            {
                uint32_t fal[4];
                #pragma unroll
                for (int mt = 0; mt < 4; mt++) {
                    ldsm4(fal, al0 + 2 * ((a_r + mt * 16) * LDA_S + a_c + ks * 16));
                    #pragma unroll
                    for (int nt = 0; nt < 4; nt++)
                        mma16816(acc[mt][nt], fal, fbh[nt]);
                }
            }
        }

        // ---- store prefetched chunk into other buffer ----
        if (has_next) {
            const int nb = buf ^ 1;
            char* db = smem + nb * BUF_BYTES;
            #pragma unroll
            for (int i = 0; i < 2; i++) {
                const uint32_t ad = ar * (LDA_S * 2) + ab + i * 16;
                *(uint4*)(db + ad)          = pah[i];
                *(uint4*)(db + ad + OFF_AL) = pal[i];
            }
            #pragma unroll
            for (int i = 0; i < 2; i++) {
                const uint32_t bd = OFF_BH + br * (LDB_S * 2) + bb + i * 16;
                *(uint4*)(db + bd) = pbh[i];
                if (USE_BL) *(uint4*)(db + bd + B_HBYTES) = pbl[i];
            }
            __syncthreads();
            buf = nb;
        }
    }

    // ---- epilogue (mapping verified R4) ----
    #pragma unroll
    for (int mt = 0; mt < 4; mt++) {
        #pragma unroll
        for (int nt = 0; nt < 4; nt++) {
            const int r = row0 + wm * 64 + mt * 16 + g;
            const int c = col0 + wn * 32 + nt * 8 + 2 * tig;
            float2 v0 = make_float2(acc[mt][nt][0], acc[mt][nt][1]);
            float2 v1 = make_float2(acc[mt][nt][2], acc[mt][nt][3]);
            if (bias) {
                const float b0 = bias[c], b1 = bias[c + 1];
                v0.x += b0; v0.y += b1;
                v1.x += b0; v1.y += b1;
            }
            if (resid) {
                const float2 r0v = *reinterpret_cast<const float2*>(&resid[(long long)r * ldc + c]);
                const float2 r1v = *reinterpret_cast<const float2*>(&resid[(long long)(r + 8) * ldc + c]);
                v0.x += r0v.x; v0.y += r0v.y;
                v1.x += r1v.x; v1.y += r1v.y;
            }
            if (Cf) {
                *reinterpret_cast<float2*>(&Cf[(long long)r * ldc + c]) = v0;
                *reinterpret_cast<float2*>(&Cf[(long long)(r + 8) * ldc + c]) = v1;
            }
            if (Ch) {
                const __half h0 = __float2half_rn(v0.x);
                const __half h1 = __float2half_rn(v0.y);
                const __half h2 = __float2half_rn(v1.x);
                const __half h3 = __float2half_rn(v1.y);
                *reinterpret_cast<__half2*>(&Ch[(long long)r * ldc + c]) =
                    __halves2half2(h0, h1);
                *reinterpret_cast<__half2*>(&Ch[(long long)(r + 8) * ldc + c]) =
                    __halves2half2(h2, h3);
                if (Cl) {
                    *reinterpret_cast<__half2*>(&Cl[(long long)r * ldc + c]) =
                        __halves2half2(__float2half_rn(v0.x - __half2float(h0)),
                                       __float2half_rn(v0.y - __half2float(h1)));
                    *reinterpret_cast<__half2*>(&Cl[(long long)(r + 8) * ldc + c]) =
                        __halves2half2(__float2half_rn(v1.x - __half2float(h2)),
                                       __float2half_rn(v1.y - __half2float(h3)));
                }
            }
        }
    }
}

// ---------------------------------------------------------------------------
// fp32 -> fp16 hi/lo elementwise split
// ---------------------------------------------------------------------------
__global__ __launch_bounds__(256) void split_kernel(
    const float* __restrict__ x, __half* __restrict__ h,
    __half* __restrict__ l, int n4)
{
    const int idx = blockIdx.x * 256 + threadIdx.x;
    if (idx >= n4) return;
    const float4 v = reinterpret_cast<const float4*>(x)[idx];
    const __half h0 = __float2half_rn(v.x), h1 = __float2half_rn(v.y);
    const __half h2 = __float2half_rn(v.z), h3 = __float2half_rn(v.w);
    reinterpret_cast<__half2*>(h)[idx * 2]     = __halves2half2(h0, h1);
    reinterpret_cast<__half2*>(h)[idx * 2 + 1] = __halves2half2(h2, h3);
    reinterpret_cast<__half2*>(l)[idx * 2] = __halves2half2(
        __float2half_rn(v.x - __half2float(h0)),
        __float2half_rn(v.y - __half2float(h1)));
    reinterpret_cast<__half2*>(l)[idx * 2 + 1] = __halves2half2(
        __float2half_rn(v.z - __half2float(h2)),
        __float2half_rn(v.w - __half2float(h3)));
}

// ---------------------------------------------------------------------------
// Row softmax over TF with fp16 hi/lo split output
// ---------------------------------------------------------------------------
__global__ __launch_bounds__(256) void softmax_split(
    const float* __restrict__ S, __half* __restrict__ H,
    __half* __restrict__ L)
{
    const long long row = blockIdx.x;
    const float* p = S + row * (long long)TF;
    const int tid = threadIdx.x;
    __shared__ float red[32];

    float4 v0 = *reinterpret_cast<const float4*>(&p[tid * 8]);
    float4 v1 = *reinterpret_cast<const float4*>(&p[tid * 8 + 4]);

    float lmax = fmaxf(fmaxf(fmaxf(v0.x, v0.y), fmaxf(v0.z, v0.w)),
                       fmaxf(fmaxf(v1.x, v1.y), fmaxf(v1.z, v1.w)));
    #pragma unroll
    for (int o = 16; o; o >>= 1) lmax = fmaxf(lmax, __shfl_xor_sync(0xffffffffu, lmax, o));
    if ((tid & 31) == 0) red[tid >> 5] = lmax;
    __syncthreads();
    if (tid < 32) {
        float v = (tid < 8) ? red[tid] : -INFINITY;
        #pragma unroll
        for (int o = 4; o; o >>= 1) v = fmaxf(v, __shfl_xor_sync(0xffffffffu, v, o));
        if (tid == 0) red[0] = v;
    }
    __syncthreads();
    const float mx = red[0];
    __syncthreads();

    v0.x = __expf(v0.x - mx); v0.y = __expf(v0.y - mx);
    v0.z = __expf(v0.z - mx); v0.w = __expf(v0.w - mx);
    v1.x = __expf(v1.x - mx); v1.y = __expf(v1.y - mx);
    v1.z = __expf(v1.z - mx); v1.w = __expf(v1.w - mx);
    float lsum = (v0.x + v0.y + v0.z + v0.w) + (v1.x + v1.y + v1.z + v1.w);
    #pragma unroll
    for (int o = 16; o; o >>= 1) lsum += __shfl_xor_sync(0xffffffffu, lsum, o);
    if ((tid & 31) == 0) red[tid >> 5] = lsum;
    __syncthreads();
    if (tid < 32) {
        float v = (tid < 8) ? red[tid] : 0.0f;
        #pragma unroll
        for (int o = 4; o; o >>= 1) v += __shfl_xor_sync(0xffffffffu, v, o);
        if (tid == 0) red[0] = v;
    }
    __syncthreads();
    const float inv = 1.0f / red[0];

    float vv[8] = { v0.x * inv, v0.y * inv, v0.z * inv, v0.w * inv,
                    v1.x * inv, v1.y * inv, v1.z * inv, v1.w * inv };
    __half* hp = H + row * (long long)TF + tid * 8;
    __half* lp = L + row * (long long)TF + tid * 8;
    #pragma unroll
    for (int e = 0; e < 8; e += 2) {
        const __half h0 = __float2half_rn(vv[e]);
        const __half h1 = __float2half_rn(vv[e + 1]);
        *reinterpret_cast<__half2*>(hp + e) = __halves2half2(h0, h1);
        *reinterpret_cast<__half2*>(lp + e) = __halves2half2(
            __float2half_rn(vv[e] - __half2float(h0)),
            __float2half_rn(vv[e + 1] - __half2float(h1)));
    }
}

// ---------------------------------------------------------------------------
// kernel_launch
// ---------------------------------------------------------------------------
extern "C" void kernel_launch(void* const* d_in, const int* in_sizes, int n_in,
                              void* d_out, int out_size)
{
    const float* q  = (const float*)d_in[0];
    const float* k  = (const float*)d_in[1];
    const float* Wq = (const float*)d_in[2];
    const float* bq = (const float*)d_in[3];
    const float* Wk = (const float*)d_in[4];
    const float* bk = (const float*)d_in[5];
    const float* Wv = (const float*)d_in[6];
    const float* bv = (const float*)d_in[7];
    float* out = (float*)d_out;

    void* p;
    cudaGetSymbolAddress(&p, g_qin);  float* qin = (float*)p;
    cudaGetSymbolAddress(&p, g_sc);   float* sc  = (float*)p;
    cudaGetSymbolAddress(&p, g_qh);   __half* qh = (__half*)p;
    cudaGetSymbolAddress(&p, g_ql);   __half* ql = (__half*)p;
    cudaGetSymbolAddress(&p, g_kh);   __half* kh = (__half*)p;
    cudaGetSymbolAddress(&p, g_kl);   __half* kl = (__half*)p;
    cudaGetSymbolAddress(&p, g_Wqh);  __half* Wqh = (__half*)p;
    cudaGetSymbolAddress(&p, g_Wql);  __half* Wql = (__half*)p;
    cudaGetSymbolAddress(&p, g_Wkh);  __half* Wkh = (__half*)p;
    cudaGetSymbolAddress(&p, g_Wkl);  __half* Wkl = (__half*)p;
    cudaGetSymbolAddress(&p, g_Wvh);  __half* Wvh = (__half*)p;
    cudaGetSymbolAddress(&p, g_Wvl);  __half* Wvl = (__half*)p;
    cudaGetSymbolAddress(&p, g_qinh); __half* qinh = (__half*)p;
    cudaGetSymbolAddress(&p, g_qinl); __half* qinl = (__half*)p;
    cudaGetSymbolAddress(&p, g_kph);  __half* kph  = (__half*)p;
    cudaGetSymbolAddress(&p, g_kpl);  __half* kpl  = (__half*)p;
    cudaGetSymbolAddress(&p, g_vph);  __half* vph  = (__half*)p;
    cudaGetSymbolAddress(&p, g_sch);  __half* sch  = (__half*)p;
    cudaGetSymbolAddress(&p, g_scl);  __half* scl  = (__half*)p;

    cudaFuncSetAttribute(mma_gemm<1>, cudaFuncAttributeMaxDynamicSharedMemorySize,
                         SMEM_GEMM);
    cudaFuncSetAttribute(mma_gemm<0>, cudaFuncAttributeMaxDynamicSharedMemorySize,
                         SMEM_GEMM);

    // 1. split inputs + weights to fp16 hi/lo
    {
        const int n4 = NELEM_QK / 4;
        split_kernel<<<n4 / 256, 256>>>(q, qh, ql, n4);
        split_kernel<<<n4 / 256, 256>>>(k, kh, kl, n4);
        const int w4 = CDIM * CDIM / 4;
        split_kernel<<<w4 / 256, 256>>>(Wq, Wqh, Wql, w4);
        split_kernel<<<w4 / 256, 256>>>(Wk, Wkh, Wkl, w4);
        split_kernel<<<w4 / 256, 256>>>(Wv, Wvh, Wvl, w4);
    }
    // 2. projections (3-pass): [32768,512] x [512,512]
    {
        const dim3 grd(CDIM / 128, (BATCH * THW) / 128, 1);
        mma_gemm<1><<<grd, 256, SMEM_GEMM>>>(qh, ql, Wqh, Wql, bq, nullptr,
                                             qin, qinh, qinl,
                                             CDIM, CDIM, CDIM, CDIM, 0, 0, 0, 0);
        mma_gemm<1><<<grd, 256, SMEM_GEMM>>>(kh, kl, Wkh, Wkl, bk, nullptr,
                                             nullptr, kph, kpl,
                                             CDIM, CDIM, CDIM, CDIM, 0, 0, 0, 0);
        mma_gemm<1><<<grd, 256, SMEM_GEMM>>>(kh, kl, Wvh, Wvl, bv, nullptr,
                                             nullptr, vph, nullptr,
                                             CDIM, CDIM, CDIM, CDIM, 0, 0, 0, 0);
    }
    // 3. scores (3-pass): qin (lda=512) x kp raw-view (ldb=TF)
    {
        const dim3 grd(TF / 128, THW / 128, BATCH);
        mma_gemm<1><<<grd, 256, SMEM_GEMM>>>(qinh, qinl, kph, kpl, nullptr, nullptr,
                                             sc, nullptr, nullptr,
                                             CDIM, CDIM, TF, TF,
                                             (long long)THW * CDIM,
                                             (long long)TF * CDIM,
                                             (long long)THW * TF, 0);
    }
    // 4. softmax + fp16 split
    softmax_split<<<BATCH * THW, 256>>>(sc, sch, scl);
    // 5. output (2-pass: attn exact x fp16(V)): attn (lda=TF) x vp (ldb=CDIM) + resid
    {
        const dim3 grd(CDIM / 128, THW / 128, BATCH);
        mma_gemm<0><<<grd, 256, SMEM_GEMM>>>(sch, scl, vph, nullptr, nullptr, qin,
                                             out, nullptr, nullptr,
                                             TF, TF, CDIM, CDIM,
                                             (long long)THW * TF,
                                             (long long)TF * CDIM,
                                             (long long)THW * CDIM,
                                             (long long)THW * CDIM);
    }
}